// round 4
// baseline (speedup 1.0000x reference)
#include <cuda_runtime.h>
#include <limits.h>

// DeepSets: out[s,f] = sx_s*W[0,f] + sy_s*W[1,f] + cnt_s*b[f]
// Linearity: segment_sum(xW+b) == segment_sum(x)@W + cnt*b.
//
// K1: warp-wide 32-ary lower_bound per boundary -> g_offsets; zeros g_partial.
// K2: point-partitioned single-wave streamer. 4736 warps each own a
//     contiguous float4 range; per-segment sums via suffix-sum trick
//     (ids sorted => <=few boundaries per warp range); REDG into g_partial.
// K3: epilogue expands (sx,sy,cnt) -> [4096,64] output.

#define FEAT_OUT 64
#define MAX_SEGMENTS 4096
#define K2_CTAS 592
#define K2_THREADS 256
#define K2_WARPS (K2_CTAS * (K2_THREADS / 32))

__device__ int   g_offsets[MAX_SEGMENTS + 1];
__device__ float g_partial[2 * MAX_SEGMENTS];

// ---------------------------------------------------------------------------
// K1: one warp per boundary target; also zero g_partial.
// ---------------------------------------------------------------------------
__global__ __launch_bounds__(128)
void find_offsets_kernel(const int* __restrict__ ids, int N, int num_segments)
{
    const int t = blockIdx.x * 128 + threadIdx.x;
    if (t < 2 * MAX_SEGMENTS) g_partial[t] = 0.0f;

    const int lane   = threadIdx.x & 31;
    const int target = blockIdx.x * 4 + (threadIdx.x >> 5);
    if (target > num_segments) return;

    int lo = 0, hi = N;
    while (hi > lo) {
        const int m = hi - lo;
        const int p = lo + (int)(((long long)m * (lane + 1)) / 33);
        const int v = __ldg(&ids[p]);
        const unsigned pred = __ballot_sync(0xFFFFFFFFu, v < target);
        const int c = __popc(pred);
        int nlo, nhi;
        if (c == 0)  nlo = lo; else nlo = lo + (int)(((long long)m * c) / 33) + 1;
        if (c == 32) nhi = hi; else nhi = lo + (int)(((long long)m * (c + 1)) / 33);
        lo = nlo; hi = nhi;
    }
    if (lane == 0) g_offsets[target] = lo;
}

// ---------------------------------------------------------------------------
// K2: single-wave point-partitioned streamer.
// ---------------------------------------------------------------------------
__device__ __forceinline__ float warp_sum(float v)
{
    #pragma unroll
    for (int o = 16; o > 0; o >>= 1) v += __shfl_xor_sync(0xFFFFFFFFu, v, o);
    return v;
}

__global__ __launch_bounds__(K2_THREADS)
void stream_kernel(const float4* __restrict__ xb,   // [N/2] pairs of points
                   const float2* __restrict__ x2,   // [N]
                   const int*    __restrict__ ids,  // [N] sorted
                   int N, int NF4)
{
    const int lane = threadIdx.x & 31;
    const int gw   = blockIdx.x * (K2_THREADS / 32) + (threadIdx.x >> 5);

    // Odd-N straggler point (handled once).
    if ((N & 1) && gw == 0 && lane == 0) {
        const int s = __ldg(&ids[N - 1]);
        const float2 p = __ldg(&x2[N - 1]);
        atomicAdd(&g_partial[2 * s],     p.x);
        atomicAdd(&g_partial[2 * s + 1], p.y);
    }

    const int Q  = (NF4 + K2_WARPS - 1) / K2_WARPS;
    const int f0 = gw * Q;
    const int f1 = min(f0 + Q, NF4);
    if (f0 >= f1) return;

    const int p0   = 2 * f0;
    const int pend = 2 * f1;
    const int s_lo = __ldg(&ids[p0]);
    const int s_hi = __ldg(&ids[pend - 1]);
    const int nseg = s_hi - s_lo + 1;

    if (nseg == 1) {
        // Pure stream: no boundary logic at all.
        float tx = 0.f, ty = 0.f;
        for (int j = f0 + lane; j < f1; j += 128) {
            const int j1 = j + 32, j2 = j + 64, j3 = j + 96;
            float4 v0 = __ldg(&xb[j]);
            float4 v1 = make_float4(0.f,0.f,0.f,0.f);
            float4 v2 = make_float4(0.f,0.f,0.f,0.f);
            float4 v3 = make_float4(0.f,0.f,0.f,0.f);
            if (j1 < f1) v1 = __ldg(&xb[j1]);
            if (j2 < f1) v2 = __ldg(&xb[j2]);
            if (j3 < f1) v3 = __ldg(&xb[j3]);
            tx += (v0.x+v0.z) + (v1.x+v1.z) + (v2.x+v2.z) + (v3.x+v3.z);
            ty += (v0.y+v0.w) + (v1.y+v1.w) + (v2.y+v2.w) + (v3.y+v3.w);
        }
        tx = warp_sum(tx); ty = warp_sum(ty);
        if (lane == 0) {
            atomicAdd(&g_partial[2 * s_lo],     tx);
            atomicAdd(&g_partial[2 * s_lo + 1], ty);
        }
    } else if (nseg == 2) {
        const int B1 = __ldg(&g_offsets[s_lo + 1]);
        const int jA = (B1 + 1) >> 1;   // pred for even point 2j   >= B1
        const int jB =  B1      >> 1;   // pred for odd  point 2j+1 >= B1
        float tx = 0.f, ty = 0.f, s1x = 0.f, s1y = 0.f;
        for (int j = f0 + lane; j < f1; j += 128) {
            const int j1 = j + 32, j2 = j + 64, j3 = j + 96;
            float4 v0 = __ldg(&xb[j]);
            float4 v1 = make_float4(0.f,0.f,0.f,0.f);
            float4 v2 = make_float4(0.f,0.f,0.f,0.f);
            float4 v3 = make_float4(0.f,0.f,0.f,0.f);
            if (j1 < f1) v1 = __ldg(&xb[j1]);
            if (j2 < f1) v2 = __ldg(&xb[j2]);
            if (j3 < f1) v3 = __ldg(&xb[j3]);
            tx += (v0.x+v0.z) + (v1.x+v1.z) + (v2.x+v2.z) + (v3.x+v3.z);
            ty += (v0.y+v0.w) + (v1.y+v1.w) + (v2.y+v2.w) + (v3.y+v3.w);
            s1x += (j  >= jA ? v0.x : 0.f) + (j  >= jB ? v0.z : 0.f)
                 + (j1 >= jA ? v1.x : 0.f) + (j1 >= jB ? v1.z : 0.f)
                 + (j2 >= jA ? v2.x : 0.f) + (j2 >= jB ? v2.z : 0.f)
                 + (j3 >= jA ? v3.x : 0.f) + (j3 >= jB ? v3.z : 0.f);
            s1y += (j  >= jA ? v0.y : 0.f) + (j  >= jB ? v0.w : 0.f)
                 + (j1 >= jA ? v1.y : 0.f) + (j1 >= jB ? v1.w : 0.f)
                 + (j2 >= jA ? v2.y : 0.f) + (j2 >= jB ? v2.w : 0.f)
                 + (j3 >= jA ? v3.y : 0.f) + (j3 >= jB ? v3.w : 0.f);
        }
        tx  = warp_sum(tx);  ty  = warp_sum(ty);
        s1x = warp_sum(s1x); s1y = warp_sum(s1y);
        if (lane == 0) {
            atomicAdd(&g_partial[2 * s_lo],           tx - s1x);
            atomicAdd(&g_partial[2 * s_lo + 1],       ty - s1y);
            atomicAdd(&g_partial[2 * (s_lo + 1)],     s1x);
            atomicAdd(&g_partial[2 * (s_lo + 1) + 1], s1y);
        }
    } else if (nseg <= 4) {
        const int B1 = __ldg(&g_offsets[s_lo + 1]);
        const int B2 = (nseg > 2) ? __ldg(&g_offsets[s_lo + 2]) : INT_MAX;
        const int B3 = (nseg > 3) ? __ldg(&g_offsets[s_lo + 3]) : INT_MAX;
        const int jA1 = (B1 + 1) >> 1, jB1 = B1 >> 1;
        const int jA2 = (B2 == INT_MAX) ? INT_MAX : (B2 + 1) >> 1;
        const int jB2 = (B2 == INT_MAX) ? INT_MAX :  B2      >> 1;
        const int jA3 = (B3 == INT_MAX) ? INT_MAX : (B3 + 1) >> 1;
        const int jB3 = (B3 == INT_MAX) ? INT_MAX :  B3      >> 1;
        float tx=0.f, ty=0.f, s1x=0.f, s1y=0.f, s2x=0.f, s2y=0.f, s3x=0.f, s3y=0.f;
        for (int j = f0 + lane; j < f1; j += 32) {
            float4 v = __ldg(&xb[j]);
            tx += v.x + v.z;  ty += v.y + v.w;
            s1x += (j >= jA1 ? v.x : 0.f) + (j >= jB1 ? v.z : 0.f);
            s1y += (j >= jA1 ? v.y : 0.f) + (j >= jB1 ? v.w : 0.f);
            s2x += (j >= jA2 ? v.x : 0.f) + (j >= jB2 ? v.z : 0.f);
            s2y += (j >= jA2 ? v.y : 0.f) + (j >= jB2 ? v.w : 0.f);
            s3x += (j >= jA3 ? v.x : 0.f) + (j >= jB3 ? v.z : 0.f);
            s3y += (j >= jA3 ? v.y : 0.f) + (j >= jB3 ? v.w : 0.f);
        }
        tx  = warp_sum(tx);  ty  = warp_sum(ty);
        s1x = warp_sum(s1x); s1y = warp_sum(s1y);
        s2x = warp_sum(s2x); s2y = warp_sum(s2y);
        s3x = warp_sum(s3x); s3y = warp_sum(s3y);
        if (lane == 0) {
            atomicAdd(&g_partial[2 * s_lo],           tx - s1x);
            atomicAdd(&g_partial[2 * s_lo + 1],       ty - s1y);
            atomicAdd(&g_partial[2 * (s_lo + 1)],     s1x - s2x);
            atomicAdd(&g_partial[2 * (s_lo + 1) + 1], s1y - s2y);
            if (nseg > 2) {
                atomicAdd(&g_partial[2 * (s_lo + 2)],     s2x - s3x);
                atomicAdd(&g_partial[2 * (s_lo + 2) + 1], s2y - s3y);
            }
            if (nseg > 3) {
                atomicAdd(&g_partial[2 * (s_lo + 3)],     s3x);
                atomicAdd(&g_partial[2 * (s_lo + 3) + 1], s3y);
            }
        }
    } else {
        // Rare slow path: per-segment re-scan (correct for any distribution).
        for (int s = s_lo; s <= s_hi; s++) {
            const int lo = max(p0,   __ldg(&g_offsets[s]));
            const int hi = min(pend, __ldg(&g_offsets[s + 1]));
            float sx = 0.f, sy = 0.f;
            for (int i = lo + lane; i < hi; i += 32) {
                float2 p = __ldg(&x2[i]);
                sx += p.x; sy += p.y;
            }
            sx = warp_sum(sx); sy = warp_sum(sy);
            if (lane == 0 && hi > lo) {
                atomicAdd(&g_partial[2 * s],     sx);
                atomicAdd(&g_partial[2 * s + 1], sy);
            }
        }
    }
}

// ---------------------------------------------------------------------------
// K3: epilogue, one thread per (segment, feature).
// ---------------------------------------------------------------------------
__global__ __launch_bounds__(256)
void epilogue_kernel(const float* __restrict__ W,   // [2,64]
                     const float* __restrict__ b,   // [64]
                     float* __restrict__ out,       // [num_segments,64]
                     int num_segments)
{
    const int t = blockIdx.x * 256 + threadIdx.x;
    if (t >= num_segments * FEAT_OUT) return;
    const int s = t >> 6;
    const int f = t & 63;
    const float sx = g_partial[2 * s];
    const float sy = g_partial[2 * s + 1];
    const float cnt = (float)(__ldg(&g_offsets[s + 1]) - __ldg(&g_offsets[s]));
    out[t] = fmaf(sx, __ldg(&W[f]), fmaf(sy, __ldg(&W[FEAT_OUT + f]), cnt * __ldg(&b[f])));
}

extern "C" void kernel_launch(void* const* d_in, const int* in_sizes, int n_in,
                              void* d_out, int out_size)
{
    const float*  xf  = (const float*)d_in[0];    // [N,2]
    const int*    ids = (const int*)d_in[1];      // [N] sorted
    const float*  W   = (const float*)d_in[2];    // [2,64]
    const float*  b   = (const float*)d_in[3];    // [64]
    float* out = (float*)d_out;

    const int N   = in_sizes[0] / 2;
    const int NF4 = N / 2;
    const int num_segments = out_size / FEAT_OUT;   // 4096

    const int nb1 = (num_segments + 1 + 3) / 4;
    find_offsets_kernel<<<nb1, 128>>>(ids, N, num_segments);

    stream_kernel<<<K2_CTAS, K2_THREADS>>>((const float4*)xf, (const float2*)xf,
                                           ids, N, NF4);

    const int nb3 = (num_segments * FEAT_OUT + 255) / 256;
    epilogue_kernel<<<nb3, 256>>>(W, b, out, num_segments);
}

// round 5
// speedup vs baseline: 1.1688x; 1.1688x over previous
#include <cuda_runtime.h>

// DeepSets: out[s,f] = sx_s*W[0,f] + sy_s*W[1,f] + cnt_s*b[f]
// Linearity: segment_sum(xW+b) == segment_sum(x)@W + cnt*b.
//
// Two launches only:
//  K2 (stream): 4864 warps each own a contiguous float4 range of x.
//     Boundary discovery is per-warp (ids sorted; 2 endpoint loads + a
//     2-round warp-wide lower_bound in its own range when needed).
//     Accumulates (sx, sy, cnt) per segment via atomics.
//  K3 (epilogue): expands to [4096,64] and RESETS accumulators, keeping the
//     zero-at-entry invariant across graph replays (device globals start 0).

#define FEAT_OUT 64
#define NSEG_MAX 4096
#define K2_CTAS 608
#define K2_THREADS 256
#define K2_WARPS (K2_CTAS * (K2_THREADS / 32))

__device__ float g_px[NSEG_MAX];
__device__ float g_py[NSEG_MAX];
__device__ int   g_cnt[NSEG_MAX];

__device__ __forceinline__ float warp_sum(float v)
{
    #pragma unroll
    for (int o = 16; o > 0; o >>= 1) v += __shfl_xor_sync(0xFFFFFFFFu, v, o);
    return v;
}

// Warp-collective lower_bound of `target` in ids[lo,hi) (sorted). All lanes
// return the same result. ~2 rounds for ranges < 1089.
__device__ __forceinline__ int warp_lower_bound(const int* __restrict__ ids,
                                                int lo, int hi, int target)
{
    const int lane = threadIdx.x & 31;
    while (hi > lo) {
        const int m = hi - lo;
        const int p = lo + (int)(((long long)m * (lane + 1)) / 33);
        const int v = __ldg(&ids[p]);
        const unsigned pred = __ballot_sync(0xFFFFFFFFu, v < target);
        const int c = __popc(pred);
        int nlo, nhi;
        if (c == 0)  nlo = lo; else nlo = lo + (int)(((long long)m * c) / 33) + 1;
        if (c == 32) nhi = hi; else nhi = lo + (int)(((long long)m * (c + 1)) / 33);
        lo = nlo; hi = nhi;
    }
    return lo;
}

// ---------------------------------------------------------------------------
// K2: single-wave point-partitioned streamer with in-warp boundary search.
// ---------------------------------------------------------------------------
__global__ __launch_bounds__(K2_THREADS)
void stream_kernel(const float4* __restrict__ xb,   // [N/2] point pairs
                   const float2* __restrict__ x2,   // [N]
                   const int*    __restrict__ ids,  // [N] sorted
                   int N, int NF4)
{
    const int lane = threadIdx.x & 31;
    const int gw   = blockIdx.x * (K2_THREADS / 32) + (threadIdx.x >> 5);

    // Odd-N straggler point.
    if ((N & 1) && gw == 0 && lane == 0) {
        const int s = __ldg(&ids[N - 1]);
        const float2 p = __ldg(&x2[N - 1]);
        atomicAdd(&g_px[s], p.x);
        atomicAdd(&g_py[s], p.y);
        atomicAdd(&g_cnt[s], 1);
    }

    const int Q  = (NF4 + K2_WARPS - 1) / K2_WARPS;
    const int f0 = gw * Q;
    const int f1 = min(f0 + Q, NF4);
    if (f0 >= f1) return;

    const int p0   = 2 * f0;
    const int pend = 2 * f1;
    const int s_lo = __ldg(&ids[p0]);
    const int s_hi = __ldg(&ids[pend - 1]);
    const int nseg = s_hi - s_lo + 1;

    if (nseg == 1) {
        // Pure stream, MLP=4.
        float tx = 0.f, ty = 0.f;
        for (int j = f0 + lane; j < f1; j += 128) {
            const int j1 = j + 32, j2 = j + 64, j3 = j + 96;
            float4 v0 = __ldg(&xb[j]);
            float4 v1 = make_float4(0.f,0.f,0.f,0.f);
            float4 v2 = make_float4(0.f,0.f,0.f,0.f);
            float4 v3 = make_float4(0.f,0.f,0.f,0.f);
            if (j1 < f1) v1 = __ldg(&xb[j1]);
            if (j2 < f1) v2 = __ldg(&xb[j2]);
            if (j3 < f1) v3 = __ldg(&xb[j3]);
            tx += (v0.x+v0.z) + (v1.x+v1.z) + (v2.x+v2.z) + (v3.x+v3.z);
            ty += (v0.y+v0.w) + (v1.y+v1.w) + (v2.y+v2.w) + (v3.y+v3.w);
        }
        tx = warp_sum(tx); ty = warp_sum(ty);
        if (lane == 0) {
            atomicAdd(&g_px[s_lo], tx);
            atomicAdd(&g_py[s_lo], ty);
            atomicAdd(&g_cnt[s_lo], pend - p0);
        }
    } else if (nseg == 2) {
        // One boundary inside the range: find it locally, then one
        // predicated streaming pass (total + suffix).
        const int B1 = warp_lower_bound(ids, p0 + 1, pend, s_lo + 1);
        const int jA = (B1 + 1) >> 1;   // even point 2j   >= B1
        const int jB =  B1      >> 1;   // odd  point 2j+1 >= B1
        float tx = 0.f, ty = 0.f, s1x = 0.f, s1y = 0.f;
        for (int j = f0 + lane; j < f1; j += 128) {
            const int j1 = j + 32, j2 = j + 64, j3 = j + 96;
            float4 v0 = __ldg(&xb[j]);
            float4 v1 = make_float4(0.f,0.f,0.f,0.f);
            float4 v2 = make_float4(0.f,0.f,0.f,0.f);
            float4 v3 = make_float4(0.f,0.f,0.f,0.f);
            if (j1 < f1) v1 = __ldg(&xb[j1]);
            if (j2 < f1) v2 = __ldg(&xb[j2]);
            if (j3 < f1) v3 = __ldg(&xb[j3]);
            tx += (v0.x+v0.z) + (v1.x+v1.z) + (v2.x+v2.z) + (v3.x+v3.z);
            ty += (v0.y+v0.w) + (v1.y+v1.w) + (v2.y+v2.w) + (v3.y+v3.w);
            s1x += (j  >= jA ? v0.x : 0.f) + (j  >= jB ? v0.z : 0.f)
                 + (j1 >= jA ? v1.x : 0.f) + (j1 >= jB ? v1.z : 0.f)
                 + (j2 >= jA ? v2.x : 0.f) + (j2 >= jB ? v2.z : 0.f)
                 + (j3 >= jA ? v3.x : 0.f) + (j3 >= jB ? v3.z : 0.f);
            s1y += (j  >= jA ? v0.y : 0.f) + (j  >= jB ? v0.w : 0.f)
                 + (j1 >= jA ? v1.y : 0.f) + (j1 >= jB ? v1.w : 0.f)
                 + (j2 >= jA ? v2.y : 0.f) + (j2 >= jB ? v2.w : 0.f)
                 + (j3 >= jA ? v3.y : 0.f) + (j3 >= jB ? v3.w : 0.f);
        }
        tx  = warp_sum(tx);  ty  = warp_sum(ty);
        s1x = warp_sum(s1x); s1y = warp_sum(s1y);
        if (lane == 0) {
            atomicAdd(&g_px[s_lo],     tx - s1x);
            atomicAdd(&g_py[s_lo],     ty - s1y);
            atomicAdd(&g_cnt[s_lo],    B1 - p0);
            atomicAdd(&g_px[s_lo + 1], s1x);
            atomicAdd(&g_py[s_lo + 1], s1y);
            atomicAdd(&g_cnt[s_lo + 1], pend - B1);
        }
    } else {
        // Rare generic path: walk segments sequentially, local searches.
        int lo = p0;
        for (int s = s_lo; s <= s_hi; s++) {
            const int hi_s = (s == s_hi) ? pend
                                         : warp_lower_bound(ids, lo, pend, s + 1);
            if (hi_s > lo) {
                float sx = 0.f, sy = 0.f;
                for (int i = lo + lane; i < hi_s; i += 32) {
                    float2 p = __ldg(&x2[i]);
                    sx += p.x; sy += p.y;
                }
                sx = warp_sum(sx); sy = warp_sum(sy);
                if (lane == 0) {
                    atomicAdd(&g_px[s], sx);
                    atomicAdd(&g_py[s], sy);
                    atomicAdd(&g_cnt[s], hi_s - lo);
                }
                lo = hi_s;
            }
        }
    }
}

// ---------------------------------------------------------------------------
// K3: epilogue + accumulator reset (preserves zero-at-entry invariant).
// One 256-thread block = exactly 4 segments.
// ---------------------------------------------------------------------------
__global__ __launch_bounds__(256)
void epilogue_kernel(const float* __restrict__ W,   // [2,64]
                     const float* __restrict__ b,   // [64]
                     float* __restrict__ out,       // [num_segments,64]
                     int num_segments)
{
    const int t = blockIdx.x * 256 + threadIdx.x;
    const int s = t >> 6;
    const int f = t & 63;
    const bool valid = (s < num_segments);

    float sx = 0.f, sy = 0.f, cnt = 0.f;
    if (valid) {
        sx  = g_px[s];
        sy  = g_py[s];
        cnt = (float)g_cnt[s];
    }
    __syncthreads();   // all reads of this block's 4 segments done
    if (valid) {
        if      (f == 0) g_px[s]  = 0.f;
        else if (f == 1) g_py[s]  = 0.f;
        else if (f == 2) g_cnt[s] = 0;
        out[t] = fmaf(sx, __ldg(&W[f]),
                 fmaf(sy, __ldg(&W[FEAT_OUT + f]), cnt * __ldg(&b[f])));
    }
}

extern "C" void kernel_launch(void* const* d_in, const int* in_sizes, int n_in,
                              void* d_out, int out_size)
{
    const float* xf  = (const float*)d_in[0];    // [N,2]
    const int*   ids = (const int*)d_in[1];      // [N] sorted
    const float* W   = (const float*)d_in[2];    // [2,64]
    const float* b   = (const float*)d_in[3];    // [64]
    float* out = (float*)d_out;

    const int N   = in_sizes[0] / 2;
    const int NF4 = N / 2;
    const int num_segments = out_size / FEAT_OUT;   // 4096

    stream_kernel<<<K2_CTAS, K2_THREADS>>>((const float4*)xf, (const float2*)xf,
                                           ids, N, NF4);

    const int nb3 = (num_segments * FEAT_OUT + 255) / 256;
    epilogue_kernel<<<nb3, 256>>>(W, b, out, num_segments);
}